// round 1
// baseline (speedup 1.0000x reference)
#include <cuda_runtime.h>
#include <math.h>

// Problem constants
#define B_   4
#define L_   4096
#define D_   1024
#define H_   16
#define W_   64
#define HD_  64
#define M_   (B_ * L_)      // 16384 tokens
#define D3_  (3 * D_)       // 3072

// Scratch (static device globals: no allocation allowed in kernel_launch)
__device__ float g_qkv [M_ * D3_];  // [M, 3D]  (3,H,HD) packed per row
__device__ float g_attn[M_ * D_ ];  // [M, D]   attention output (token-major, heads concat)
__device__ float g_y   [M_ * D_ ];  // [M, D]   proj + bias + residual (pre-LN)

// ---------------------------------------------------------------------------
// Tiled SGEMM (NT): C[M,N] = A[M,K] * Bw[N,K]^T + bias (+ residual if MODE==1)
// BM=BN=128, BK=16, 256 threads, 8x8 per thread, register-prefetch pipeline.
// ---------------------------------------------------------------------------
template<int MODE>
__global__ __launch_bounds__(256, 2)
void sgemm_nt(const float* __restrict__ A, const float* __restrict__ Bw,
              const float* __restrict__ bias, const float* __restrict__ res,
              float* __restrict__ C, int N, int K)
{
    constexpr int BM = 128, BN = 128, BK = 16;
    __shared__ __align__(16) float As[BK][BM + 4];
    __shared__ __align__(16) float Bs[BK][BN + 4];

    const int tid  = threadIdx.x;
    const int tx   = tid & 15;          // 0..15 -> N direction
    const int ty   = tid >> 4;          // 0..15 -> M direction
    const int m0   = blockIdx.y * BM;
    const int n0   = blockIdx.x * BN;
    const int lrow = tid >> 2;          // 0..63
    const int lkq  = tid & 3;           // 0..3  (float4 within BK)

    const float* Ag  = A  + (size_t)(m0 + lrow) * K + lkq * 4;
    const float* Ag2 = Ag + (size_t)64 * K;
    const float* Bg  = Bw + (size_t)(n0 + lrow) * K + lkq * 4;
    const float* Bg2 = Bg + (size_t)64 * K;

    float4 ra0 = *(const float4*)Ag;
    float4 ra1 = *(const float4*)Ag2;
    float4 rb0 = *(const float4*)Bg;
    float4 rb1 = *(const float4*)Bg2;

    float acc[8][8];
    #pragma unroll
    for (int i = 0; i < 8; i++)
        #pragma unroll
        for (int j = 0; j < 8; j++) acc[i][j] = 0.0f;

    const int nkt = K / BK;
    for (int kt = 0; kt < nkt; ++kt) {
        // commit prefetched tile to smem (A transposed to [k][m])
        As[lkq*4+0][lrow]    = ra0.x;  As[lkq*4+1][lrow]    = ra0.y;
        As[lkq*4+2][lrow]    = ra0.z;  As[lkq*4+3][lrow]    = ra0.w;
        As[lkq*4+0][lrow+64] = ra1.x;  As[lkq*4+1][lrow+64] = ra1.y;
        As[lkq*4+2][lrow+64] = ra1.z;  As[lkq*4+3][lrow+64] = ra1.w;
        Bs[lkq*4+0][lrow]    = rb0.x;  Bs[lkq*4+1][lrow]    = rb0.y;
        Bs[lkq*4+2][lrow]    = rb0.z;  Bs[lkq*4+3][lrow]    = rb0.w;
        Bs[lkq*4+0][lrow+64] = rb1.x;  Bs[lkq*4+1][lrow+64] = rb1.y;
        Bs[lkq*4+2][lrow+64] = rb1.z;  Bs[lkq*4+3][lrow+64] = rb1.w;
        __syncthreads();

        if (kt + 1 < nkt) {             // prefetch next tile (overlaps compute)
            const int off = (kt + 1) * BK;
            ra0 = *(const float4*)(Ag  + off);
            ra1 = *(const float4*)(Ag2 + off);
            rb0 = *(const float4*)(Bg  + off);
            rb1 = *(const float4*)(Bg2 + off);
        }

        #pragma unroll
        for (int kk = 0; kk < BK; ++kk) {
            float a[8], b[8];
            *(float4*)&a[0] = *(const float4*)&As[kk][ty*8];
            *(float4*)&a[4] = *(const float4*)&As[kk][ty*8 + 4];
            *(float4*)&b[0] = *(const float4*)&Bs[kk][tx*8];
            *(float4*)&b[4] = *(const float4*)&Bs[kk][tx*8 + 4];
            #pragma unroll
            for (int i = 0; i < 8; i++)
                #pragma unroll
                for (int j = 0; j < 8; j++)
                    acc[i][j] = fmaf(a[i], b[j], acc[i][j]);
        }
        __syncthreads();
    }

    // epilogue
    #pragma unroll
    for (int i = 0; i < 8; i++) {
        const int row = m0 + ty*8 + i;
        #pragma unroll
        for (int j = 0; j < 8; j += 4) {
            const int col = n0 + tx*8 + j;
            float4 bb = *(const float4*)(bias + col);
            float4 v;
            v.x = acc[i][j+0] + bb.x;
            v.y = acc[i][j+1] + bb.y;
            v.z = acc[i][j+2] + bb.z;
            v.w = acc[i][j+3] + bb.w;
            if (MODE == 1) {
                float4 rr = *(const float4*)(res + (size_t)row * N + col);
                v.x += rr.x; v.y += rr.y; v.z += rr.z; v.w += rr.w;
            }
            *(float4*)(C + (size_t)row * N + col) = v;
        }
    }
}

// ---------------------------------------------------------------------------
// Windowed attention: one CTA per (b,h,window). 64x64x64 fused in SMEM.
//   sA: Q^T [d][i] -> later P^T [j][i]
//   sB: K^T [d][j] -> later V   [j][d]
// ---------------------------------------------------------------------------
__global__ __launch_bounds__(256)
void attn_win(const float* __restrict__ qkv, float* __restrict__ out)
{
    __shared__ __align__(16) float sA[64 * 68];
    __shared__ __align__(16) float sB[64 * 68];
    __shared__ float sInv[64];

    const int wid = blockIdx.x;
    const int n = wid & 63;
    const int h = (wid >> 6) & 15;
    const int b = wid >> 10;
    const int tok0 = b * L_ + n * W_;
    const float* basep = qkv + (size_t)tok0 * D3_ + h * HD_;

    const int t = threadIdx.x;

    // Load Q,K (transposed into smem) and V (to registers)
    float4 vreg[4];
    #pragma unroll
    for (int it = 0; it < 4; ++it) {
        const int lin = t + it * 256;            // 0..1023
        const int i  = lin >> 4;                 // token in window
        const int d4 = lin & 15;                 // float4 within head dim
        const float* rp = basep + (size_t)i * D3_;
        float4 q4 = *(const float4*)(rp +        d4 * 4);
        float4 k4 = *(const float4*)(rp + D_  + d4 * 4);
        vreg[it]  = *(const float4*)(rp + 2*D_ + d4 * 4);
        sA[(d4*4+0)*68 + i] = q4.x; sA[(d4*4+1)*68 + i] = q4.y;
        sA[(d4*4+2)*68 + i] = q4.z; sA[(d4*4+3)*68 + i] = q4.w;
        sB[(d4*4+0)*68 + i] = k4.x; sB[(d4*4+1)*68 + i] = k4.y;
        sB[(d4*4+2)*68 + i] = k4.z; sB[(d4*4+3)*68 + i] = k4.w;
    }
    __syncthreads();

    // S[i][j] = sum_d Q^T[d][i] * K^T[d][j], 4x4 per thread
    const int tx = t & 15, ty = t >> 4;
    const int i0 = ty * 4, j0 = tx * 4;
    float acc[4][4];
    #pragma unroll
    for (int i = 0; i < 4; i++)
        #pragma unroll
        for (int j = 0; j < 4; j++) acc[i][j] = 0.0f;

    #pragma unroll
    for (int d = 0; d < 64; ++d) {
        float4 a  = *(const float4*)&sA[d*68 + i0];
        float4 bq = *(const float4*)&sB[d*68 + j0];
        const float av[4] = {a.x, a.y, a.z, a.w};
        const float bv[4] = {bq.x, bq.y, bq.z, bq.w};
        #pragma unroll
        for (int i = 0; i < 4; i++)
            #pragma unroll
            for (int j = 0; j < 4; j++)
                acc[i][j] = fmaf(av[i], bv[j], acc[i][j]);
    }
    __syncthreads();   // Q,K now dead

    // Store scaled S transposed into sA ([j][i]); V from regs into sB ([j][d])
    const float scale = 0.125f;   // HD^-0.5
    #pragma unroll
    for (int jj = 0; jj < 4; jj++) {
        float4 col;
        col.x = acc[0][jj] * scale; col.y = acc[1][jj] * scale;
        col.z = acc[2][jj] * scale; col.w = acc[3][jj] * scale;
        *(float4*)&sA[(j0 + jj)*68 + i0] = col;
    }
    #pragma unroll
    for (int it = 0; it < 4; ++it) {
        const int lin = t + it * 256;
        const int i = lin >> 4, d4 = lin & 15;
        *(float4*)&sB[i*68 + d4*4] = vreg[it];
    }
    __syncthreads();

    // Softmax along j for each query i (thread i owns column i of sA)
    if (t < 64) {
        float m = -1e30f;
        #pragma unroll 8
        for (int j = 0; j < 64; j++) m = fmaxf(m, sA[j*68 + t]);
        float s = 0.0f;
        #pragma unroll 8
        for (int j = 0; j < 64; j++) {
            float e = __expf(sA[j*68 + t] - m);
            sA[j*68 + t] = e;
            s += e;
        }
        sInv[t] = 1.0f / s;
    }
    __syncthreads();

    // O[i][d] = (1/s_i) * sum_j E[j][i] * V[j][d], 4x4 per thread (d0 = j0)
    float o[4][4];
    #pragma unroll
    for (int i = 0; i < 4; i++)
        #pragma unroll
        for (int j = 0; j < 4; j++) o[i][j] = 0.0f;

    #pragma unroll
    for (int j = 0; j < 64; ++j) {
        float4 p  = *(const float4*)&sA[j*68 + i0];
        float4 vv = *(const float4*)&sB[j*68 + j0];
        const float pv[4] = {p.x, p.y, p.z, p.w};
        const float vvv[4] = {vv.x, vv.y, vv.z, vv.w};
        #pragma unroll
        for (int i = 0; i < 4; i++)
            #pragma unroll
            for (int d = 0; d < 4; d++)
                o[i][d] = fmaf(pv[i], vvv[d], o[i][d]);
    }

    #pragma unroll
    for (int i = 0; i < 4; i++) {
        const float inv = sInv[i0 + i];
        float4 r;
        r.x = o[i][0] * inv; r.y = o[i][1] * inv;
        r.z = o[i][2] * inv; r.w = o[i][3] * inv;
        *(float4*)(out + (size_t)(tok0 + i0 + i) * D_ + h * HD_ + j0) = r;
    }
}

// ---------------------------------------------------------------------------
// LayerNorm: one CTA (256 threads) per token row of 1024 floats.
// ---------------------------------------------------------------------------
__global__ __launch_bounds__(256)
void ln_kernel(const float* __restrict__ y, const float* __restrict__ gamma,
               const float* __restrict__ beta, float* __restrict__ out)
{
    const int row = blockIdx.x;
    const int t = threadIdx.x;
    const float4 v = ((const float4*)(y + (size_t)row * D_))[t];

    float s  = v.x + v.y + v.z + v.w;
    float s2 = v.x*v.x + v.y*v.y + v.z*v.z + v.w*v.w;

    #pragma unroll
    for (int off = 16; off > 0; off >>= 1) {
        s  += __shfl_xor_sync(0xffffffffu, s,  off);
        s2 += __shfl_xor_sync(0xffffffffu, s2, off);
    }
    __shared__ float ws[8], ws2[8];
    const int warp = t >> 5, lane = t & 31;
    if (lane == 0) { ws[warp] = s; ws2[warp] = s2; }
    __syncthreads();
    float S = 0.0f, S2 = 0.0f;
    #pragma unroll
    for (int w = 0; w < 8; w++) { S += ws[w]; S2 += ws2[w]; }

    const float mean = S * (1.0f / D_);
    const float var  = S2 * (1.0f / D_) - mean * mean;
    const float rstd = rsqrtf(var + 1e-5f);

    const float4 g = ((const float4*)gamma)[t];
    const float4 be = ((const float4*)beta)[t];
    float4 o;
    o.x = (v.x - mean) * rstd * g.x + be.x;
    o.y = (v.y - mean) * rstd * g.y + be.y;
    o.z = (v.z - mean) * rstd * g.z + be.z;
    o.w = (v.w - mean) * rstd * g.w + be.w;
    ((float4*)(out + (size_t)row * D_))[t] = o;
}

// ---------------------------------------------------------------------------
extern "C" void kernel_launch(void* const* d_in, const int* in_sizes, int n_in,
                              void* d_out, int out_size)
{
    const float* x     = (const float*)d_in[0];
    const float* Wqkv  = (const float*)d_in[1];
    const float* bqkv  = (const float*)d_in[2];
    const float* Wproj = (const float*)d_in[3];
    const float* bproj = (const float*)d_in[4];
    const float* gamma = (const float*)d_in[5];
    const float* beta  = (const float*)d_in[6];
    float* out = (float*)d_out;

    float *qkv_p, *attn_p, *y_p;
    cudaGetSymbolAddress((void**)&qkv_p,  g_qkv);
    cudaGetSymbolAddress((void**)&attn_p, g_attn);
    cudaGetSymbolAddress((void**)&y_p,    g_y);

    // 1) QKV projection: [16384,3072] = x @ Wqkv^T + bqkv
    sgemm_nt<0><<<dim3(D3_/128, M_/128), 256>>>(x, Wqkv, bqkv, nullptr,
                                                qkv_p, D3_, D_);
    // 2) Windowed attention: 4096 windows (B*H*nw)
    attn_win<<<B_ * H_ * (L_ / W_), 256>>>(qkv_p, attn_p);
    // 3) Output projection + bias + residual
    sgemm_nt<1><<<dim3(D_/128, M_/128), 256>>>(attn_p, Wproj, bproj, x,
                                               y_p, D_, D_);
    // 4) LayerNorm -> output
    ln_kernel<<<M_, 256>>>(y_p, gamma, beta, out);
}

// round 15
// speedup vs baseline: 1.5877x; 1.5877x over previous
#include <cuda_runtime.h>
#include <math.h>
#include <stdint.h>

// Problem constants
#define B_   4
#define L_   4096
#define D_   1024
#define H_   16
#define W_   64
#define HD_  64
#define M_   (B_ * L_)      // 16384 tokens
#define D3_  (3 * D_)       // 3072

// Scratch (static device globals: no allocation allowed in kernel_launch)
__device__ float g_qkv [M_ * D3_];  // [M, 3D]
__device__ float g_attn[M_ * D_ ];  // [M, D]
__device__ float g_y   [M_ * D_ ];  // [M, D]

// ---------------------------------------------------------------------------
// TF32 tensor-core GEMM (NT): C[M,N] = A[M,K] * Bw[N,K]^T + bias (+res MODE=1)
// CTA tile 128x128x16, 256 threads = 8 warps, warp tile 64x32 (4x4 m16n8k8).
// Smem k-major with pad 8 -> conflict-free fragment loads.
// Double-buffered smem: ONE __syncthreads per K-tile.
// ---------------------------------------------------------------------------
#define LDS_  136   // 128 + 8 pad

__device__ __forceinline__ uint32_t f2tf32(float v) {
    uint32_t u;
    asm volatile("cvt.rna.tf32.f32 %0, %1;" : "=r"(u) : "f"(v));
    return u;
}

__device__ __forceinline__ void mma_tf32(float acc[4], const uint32_t a[4],
                                         const uint32_t b[2]) {
    asm volatile(
        "mma.sync.aligned.m16n8k8.row.col.f32.tf32.tf32.f32 "
        "{%0,%1,%2,%3}, {%4,%5,%6,%7}, {%8,%9}, {%0,%1,%2,%3};\n"
        : "+f"(acc[0]), "+f"(acc[1]), "+f"(acc[2]), "+f"(acc[3])
        : "r"(a[0]), "r"(a[1]), "r"(a[2]), "r"(a[3]), "r"(b[0]), "r"(b[1]));
}

template<int MODE>
__global__ __launch_bounds__(256, 2)
void gemm_tf32(const float* __restrict__ A, const float* __restrict__ Bw,
               const float* __restrict__ bias, const float* __restrict__ res,
               float* __restrict__ C, int N, int K)
{
    __shared__ __align__(16) uint32_t As[2][16 * LDS_];
    __shared__ __align__(16) uint32_t Bs[2][16 * LDS_];

    const int tid   = threadIdx.x;
    const int lane  = tid & 31;
    const int warp  = tid >> 5;
    const int g     = lane >> 2;          // group id 0..7
    const int c     = lane & 3;           // thread-in-group 0..3
    const int mWarp = (warp >> 2) * 64;   // 0 or 64
    const int nWarp = (warp & 3) * 32;    // 0,32,64,96
    const int m0    = blockIdx.y * 128;
    const int n0    = blockIdx.x * 128;

    // global load mapping: each thread loads 2 float4 per operand per K-tile
    const int lrow = tid & 127;           // row within tile
    const int kq0  = tid >> 7;            // 0 or 1 (float4 index in K)
    const float* Ag = A  + (size_t)(m0 + lrow) * K + kq0 * 4;
    const float* Bg = Bw + (size_t)(n0 + lrow) * K + kq0 * 4;

    float4 ra0 = *(const float4*)Ag;
    float4 ra1 = *(const float4*)(Ag + 8);
    float4 rb0 = *(const float4*)Bg;
    float4 rb1 = *(const float4*)(Bg + 8);

    float acc[4][4][4];
    #pragma unroll
    for (int mt = 0; mt < 4; mt++)
        #pragma unroll
        for (int nt = 0; nt < 4; nt++)
            #pragma unroll
            for (int r = 0; r < 4; r++) acc[mt][nt][r] = 0.0f;

    const int nkt = K / 16;
    for (int kt = 0; kt < nkt; ++kt) {
        const int p = kt & 1;
        uint32_t* Asb = As[p];
        uint32_t* Bsb = Bs[p];
        // commit prefetched data (transpose to k-major, round to tf32)
        {
            const int k0 = kq0 * 4, k1 = kq0 * 4 + 8;
            Asb[(k0+0)*LDS_ + lrow] = f2tf32(ra0.x);
            Asb[(k0+1)*LDS_ + lrow] = f2tf32(ra0.y);
            Asb[(k0+2)*LDS_ + lrow] = f2tf32(ra0.z);
            Asb[(k0+3)*LDS_ + lrow] = f2tf32(ra0.w);
            Asb[(k1+0)*LDS_ + lrow] = f2tf32(ra1.x);
            Asb[(k1+1)*LDS_ + lrow] = f2tf32(ra1.y);
            Asb[(k1+2)*LDS_ + lrow] = f2tf32(ra1.z);
            Asb[(k1+3)*LDS_ + lrow] = f2tf32(ra1.w);
            Bsb[(k0+0)*LDS_ + lrow] = f2tf32(rb0.x);
            Bsb[(k0+1)*LDS_ + lrow] = f2tf32(rb0.y);
            Bsb[(k0+2)*LDS_ + lrow] = f2tf32(rb0.z);
            Bsb[(k0+3)*LDS_ + lrow] = f2tf32(rb0.w);
            Bsb[(k1+0)*LDS_ + lrow] = f2tf32(rb1.x);
            Bsb[(k1+1)*LDS_ + lrow] = f2tf32(rb1.y);
            Bsb[(k1+2)*LDS_ + lrow] = f2tf32(rb1.z);
            Bsb[(k1+3)*LDS_ + lrow] = f2tf32(rb1.w);
        }
        __syncthreads();   // single sync per tile: double buffer makes it safe

        if (kt + 1 < nkt) {
            const int off = (kt + 1) * 16;
            ra0 = *(const float4*)(Ag + off);
            ra1 = *(const float4*)(Ag + off + 8);
            rb0 = *(const float4*)(Bg + off);
            rb1 = *(const float4*)(Bg + off + 8);
        }

        #pragma unroll
        for (int kk = 0; kk < 16; kk += 8) {
            uint32_t af[4][4], bf[4][2];
            #pragma unroll
            for (int mt = 0; mt < 4; mt++) {
                const int mr = mWarp + mt * 16 + g;
                af[mt][0] = Asb[(kk + c    ) * LDS_ + mr];
                af[mt][1] = Asb[(kk + c    ) * LDS_ + mr + 8];
                af[mt][2] = Asb[(kk + c + 4) * LDS_ + mr];
                af[mt][3] = Asb[(kk + c + 4) * LDS_ + mr + 8];
            }
            #pragma unroll
            for (int nt = 0; nt < 4; nt++) {
                const int nc = nWarp + nt * 8 + g;
                bf[nt][0] = Bsb[(kk + c    ) * LDS_ + nc];
                bf[nt][1] = Bsb[(kk + c + 4) * LDS_ + nc];
            }
            #pragma unroll
            for (int mt = 0; mt < 4; mt++)
                #pragma unroll
                for (int nt = 0; nt < 4; nt++)
                    mma_tf32(acc[mt][nt], af[mt], bf[nt]);
        }
        // no second sync: next iteration writes the OTHER buffer
    }

    // epilogue: d0,d1 -> (row, col..col+1); d2,d3 -> (row+8, col..col+1)
    #pragma unroll
    for (int mt = 0; mt < 4; mt++) {
        const int row = m0 + mWarp + mt * 16 + g;
        #pragma unroll
        for (int nt = 0; nt < 4; nt++) {
            const int col = n0 + nWarp + nt * 8 + c * 2;
            const float b0 = bias[col], b1 = bias[col + 1];
            float2 v0, v1;
            v0.x = acc[mt][nt][0] + b0;  v0.y = acc[mt][nt][1] + b1;
            v1.x = acc[mt][nt][2] + b0;  v1.y = acc[mt][nt][3] + b1;
            if (MODE == 1) {
                float2 r0 = *(const float2*)(res + (size_t)row * N + col);
                float2 r1 = *(const float2*)(res + (size_t)(row + 8) * N + col);
                v0.x += r0.x; v0.y += r0.y;
                v1.x += r1.x; v1.y += r1.y;
            }
            *(float2*)(C + (size_t)row * N + col)       = v0;
            *(float2*)(C + (size_t)(row + 8) * N + col) = v1;
        }
    }
}

// ---------------------------------------------------------------------------
// Windowed attention: one CTA per (b,h,window). 64x64x64 fused in SMEM.
// ---------------------------------------------------------------------------
__global__ __launch_bounds__(256)
void attn_win(const float* __restrict__ qkv, float* __restrict__ out)
{
    __shared__ __align__(16) float sA[64 * 68];
    __shared__ __align__(16) float sB[64 * 68];
    __shared__ float sInv[64];

    const int wid = blockIdx.x;
    const int n = wid & 63;
    const int h = (wid >> 6) & 15;
    const int b = wid >> 10;
    const int tok0 = b * L_ + n * W_;
    const float* basep = qkv + (size_t)tok0 * D3_ + h * HD_;

    const int t = threadIdx.x;

    float4 vreg[4];
    #pragma unroll
    for (int it = 0; it < 4; ++it) {
        const int lin = t + it * 256;
        const int i  = lin >> 4;
        const int d4 = lin & 15;
        const float* rp = basep + (size_t)i * D3_;
        float4 q4 = *(const float4*)(rp +        d4 * 4);
        float4 k4 = *(const float4*)(rp + D_  + d4 * 4);
        vreg[it]  = *(const float4*)(rp + 2*D_ + d4 * 4);
        sA[(d4*4+0)*68 + i] = q4.x; sA[(d4*4+1)*68 + i] = q4.y;
        sA[(d4*4+2)*68 + i] = q4.z; sA[(d4*4+3)*68 + i] = q4.w;
        sB[(d4*4+0)*68 + i] = k4.x; sB[(d4*4+1)*68 + i] = k4.y;
        sB[(d4*4+2)*68 + i] = k4.z; sB[(d4*4+3)*68 + i] = k4.w;
    }
    __syncthreads();

    const int tx = t & 15, ty = t >> 4;
    const int i0 = ty * 4, j0 = tx * 4;
    float acc[4][4];
    #pragma unroll
    for (int i = 0; i < 4; i++)
        #pragma unroll
        for (int j = 0; j < 4; j++) acc[i][j] = 0.0f;

    #pragma unroll
    for (int d = 0; d < 64; ++d) {
        float4 a  = *(const float4*)&sA[d*68 + i0];
        float4 bq = *(const float4*)&sB[d*68 + j0];
        const float av[4] = {a.x, a.y, a.z, a.w};
        const float bv[4] = {bq.x, bq.y, bq.z, bq.w};
        #pragma unroll
        for (int i = 0; i < 4; i++)
            #pragma unroll
            for (int j = 0; j < 4; j++)
                acc[i][j] = fmaf(av[i], bv[j], acc[i][j]);
    }
    __syncthreads();

    const float scale = 0.125f;
    #pragma unroll
    for (int jj = 0; jj < 4; jj++) {
        float4 col;
        col.x = acc[0][jj] * scale; col.y = acc[1][jj] * scale;
        col.z = acc[2][jj] * scale; col.w = acc[3][jj] * scale;
        *(float4*)&sA[(j0 + jj)*68 + i0] = col;
    }
    #pragma unroll
    for (int it = 0; it < 4; ++it) {
        const int lin = t + it * 256;
        const int i = lin >> 4, d4 = lin & 15;
        *(float4*)&sB[i*68 + d4*4] = vreg[it];
    }
    __syncthreads();

    if (t < 64) {
        float m = -1e30f;
        #pragma unroll 8
        for (int j = 0; j < 64; j++) m = fmaxf(m, sA[j*68 + t]);
        float s = 0.0f;
        #pragma unroll 8
        for (int j = 0; j < 64; j++) {
            float e = __expf(sA[j*68 + t] - m);
            sA[j*68 + t] = e;
            s += e;
        }
        sInv[t] = 1.0f / s;
    }
    __syncthreads();

    float o[4][4];
    #pragma unroll
    for (int i = 0; i < 4; i++)
        #pragma unroll
        for (int j = 0; j < 4; j++) o[i][j] = 0.0f;

    #pragma unroll
    for (int j = 0; j < 64; ++j) {
        float4 p  = *(const float4*)&sA[j*68 + i0];
        float4 vv = *(const float4*)&sB[j*68 + j0];
        const float pv[4]  = {p.x, p.y, p.z, p.w};
        const float vvv[4] = {vv.x, vv.y, vv.z, vv.w};
        #pragma unroll
        for (int i = 0; i < 4; i++)
            #pragma unroll
            for (int d = 0; d < 4; d++)
                o[i][d] = fmaf(pv[i], vvv[d], o[i][d]);
    }

    #pragma unroll
    for (int i = 0; i < 4; i++) {
        const float inv = sInv[i0 + i];
        float4 r;
        r.x = o[i][0] * inv; r.y = o[i][1] * inv;
        r.z = o[i][2] * inv; r.w = o[i][3] * inv;
        *(float4*)(out + (size_t)(tok0 + i0 + i) * D_ + h * HD_ + j0) = r;
    }
}

// ---------------------------------------------------------------------------
// LayerNorm: one CTA (256 threads) per token row of 1024 floats.
// ---------------------------------------------------------------------------
__global__ __launch_bounds__(256)
void ln_kernel(const float* __restrict__ y, const float* __restrict__ gamma,
               const float* __restrict__ beta, float* __restrict__ out)
{
    const int row = blockIdx.x;
    const int t = threadIdx.x;
    const float4 v = ((const float4*)(y + (size_t)row * D_))[t];

    float s  = v.x + v.y + v.z + v.w;
    float s2 = v.x*v.x + v.y*v.y + v.z*v.z + v.w*v.w;

    #pragma unroll
    for (int off = 16; off > 0; off >>= 1) {
        s  += __shfl_xor_sync(0xffffffffu, s,  off);
        s2 += __shfl_xor_sync(0xffffffffu, s2, off);
    }
    __shared__ float ws[8], ws2[8];
    const int warp = t >> 5, lane = t & 31;
    if (lane == 0) { ws[warp] = s; ws2[warp] = s2; }
    __syncthreads();
    float S = 0.0f, S2 = 0.0f;
    #pragma unroll
    for (int w = 0; w < 8; w++) { S += ws[w]; S2 += ws2[w]; }

    const float mean = S * (1.0f / D_);
    const float var  = S2 * (1.0f / D_) - mean * mean;
    const float rstd = rsqrtf(var + 1e-5f);

    const float4 gm = ((const float4*)gamma)[t];
    const float4 be = ((const float4*)beta)[t];
    float4 o;
    o.x = (v.x - mean) * rstd * gm.x + be.x;
    o.y = (v.y - mean) * rstd * gm.y + be.y;
    o.z = (v.z - mean) * rstd * gm.z + be.z;
    o.w = (v.w - mean) * rstd * gm.w + be.w;
    ((float4*)(out + (size_t)row * D_))[t] = o;
}

// ---------------------------------------------------------------------------
extern "C" void kernel_launch(void* const* d_in, const int* in_sizes, int n_in,
                              void* d_out, int out_size)
{
    const float* x     = (const float*)d_in[0];
    const float* Wqkv  = (const float*)d_in[1];
    const float* bqkv  = (const float*)d_in[2];
    const float* Wproj = (const float*)d_in[3];
    const float* bproj = (const float*)d_in[4];
    const float* gamma = (const float*)d_in[5];
    const float* beta  = (const float*)d_in[6];
    float* out = (float*)d_out;

    float *qkv_p, *attn_p, *y_p;
    cudaGetSymbolAddress((void**)&qkv_p,  g_qkv);
    cudaGetSymbolAddress((void**)&attn_p, g_attn);
    cudaGetSymbolAddress((void**)&y_p,    g_y);

    // 1) QKV projection: [16384,3072] = x @ Wqkv^T + bqkv   (TF32 tensor core)
    gemm_tf32<0><<<dim3(D3_/128, M_/128), 256>>>(x, Wqkv, bqkv, nullptr,
                                                 qkv_p, D3_, D_);
    // 2) Windowed attention: 4096 windows (B*H*nw)
    attn_win<<<B_ * H_ * (L_ / W_), 256>>>(qkv_p, attn_p);
    // 3) Output projection + bias + residual                (TF32 tensor core)
    gemm_tf32<1><<<dim3(D_/128, M_/128), 256>>>(attn_p, Wproj, bproj, x,
                                                y_p, D_, D_);
    // 4) LayerNorm -> output
    ln_kernel<<<M_, 256>>>(y_p, gamma, beta, out);
}